// round 5
// baseline (speedup 1.0000x reference)
#include <cuda_runtime.h>
#include <cstdint>

#define NN 50000
#define NE 400000
#define DIM 128
#define SS 36   // smem row stride (floats); 36%4==0 (float4 stores), 36%32==4 -> conflict-free frags

// Scratch (allocation-free rule: __device__ globals)
__device__ float g_h[NN * DIM];
__device__ float g_agg[NN * DIM];
__device__ float g_deg[NN];

// ---------------------------------------------------------------------------
__device__ __forceinline__ void split_tf32(float a, uint32_t& hi, uint32_t& lo)
{
    uint32_t h;
    asm("cvt.rna.tf32.f32 %0, %1;" : "=r"(h) : "f"(a));
    float r = a - __uint_as_float(h);          // exact in f32
    asm("cvt.rna.tf32.f32 %0, %1;" : "=r"(lo) : "f"(r));
    hi = h;
}

__device__ __forceinline__ void mma8(float* c,
                                     uint32_t a0, uint32_t a1, uint32_t a2, uint32_t a3,
                                     uint32_t b0, uint32_t b1)
{
    asm volatile(
        "mma.sync.aligned.m16n8k8.row.col.f32.tf32.tf32.f32 "
        "{%0,%1,%2,%3}, {%4,%5,%6,%7}, {%8,%9}, {%0,%1,%2,%3};"
        : "+f"(c[0]), "+f"(c[1]), "+f"(c[2]), "+f"(c[3])
        : "r"(a0), "r"(a1), "r"(a2), "r"(a3), "r"(b0), "r"(b1));
}

// ---------------------------------------------------------------------------
// Tensor-core GEMM with pre-split tf32 operands in smem.
// C[m,n] = act( sum_k A[m,k] * W[n,k] + bias[n] )
// BM=128, BN=128, BK=32 slabs. 256 threads = 8 warps (4 m-bands x 2 n-bands).
// MODE 0: A = x, relu, C = g_h
// MODE 1: A = g_agg/max(deg,1) + g_h (fused on load), C = d_out
// ---------------------------------------------------------------------------
template <int MODE>
__global__ __launch_bounds__(256, 2)
void gemm_tc(const float* __restrict__ A,
             const float* __restrict__ W,
             const float* __restrict__ bias,
             float* __restrict__ C)
{
    extern __shared__ uint32_t smem[];
    uint32_t* Ahi_s = smem;                 // 128*SS
    uint32_t* Alo_s = smem + 128 * SS;
    uint32_t* Whi_s = smem + 2 * 128 * SS;
    uint32_t* Wlo_s = smem + 3 * 128 * SS;

    const int tid    = threadIdx.x;
    const int lane   = tid & 31;
    const int wid    = tid >> 5;
    const int warp_m = wid >> 1;   // 0..3 -> 32-row band
    const int warp_n = wid & 1;    // 0..1 -> 64-col band
    const int m0     = blockIdx.x * 128;

    float acc[2][8][4];
#pragma unroll
    for (int mt = 0; mt < 2; mt++)
#pragma unroll
        for (int nt = 0; nt < 8; nt++)
#pragma unroll
            for (int i = 0; i < 4; i++) acc[mt][nt][i] = 0.0f;

    const int srow = tid >> 3;          // 0..31
    const int scol = (tid & 7) * 4;     // 0,4,...,28

    for (int k0 = 0; k0 < DIM; k0 += 32) {
        // ---- stage + split A and W slabs ----
#pragma unroll
        for (int s = 0; s < 4; s++) {
            int row = srow + s * 32;    // 0..127
            int gm  = m0 + row;
            float4 v = make_float4(0.f, 0.f, 0.f, 0.f);
            if (gm < NN) {
                int gi = gm * DIM + k0 + scol;
                if (MODE == 0) {
                    v = *(const float4*)&A[gi];
                } else {
                    float d   = g_deg[gm];
                    float inv = 1.0f / fmaxf(d, 1.0f);
                    float4 ag = *(const float4*)&g_agg[gi];
                    float4 hh = *(const float4*)&g_h[gi];
                    v.x = fmaf(ag.x, inv, hh.x);
                    v.y = fmaf(ag.y, inv, hh.y);
                    v.z = fmaf(ag.z, inv, hh.z);
                    v.w = fmaf(ag.w, inv, hh.w);
                }
            }
            uint4 hi, lo;
            split_tf32(v.x, hi.x, lo.x);
            split_tf32(v.y, hi.y, lo.y);
            split_tf32(v.z, hi.z, lo.z);
            split_tf32(v.w, hi.w, lo.w);
            *(uint4*)&Ahi_s[row * SS + scol] = hi;
            *(uint4*)&Alo_s[row * SS + scol] = lo;

            float4 wv = *(const float4*)&W[row * DIM + k0 + scol];
            split_tf32(wv.x, hi.x, lo.x);
            split_tf32(wv.y, hi.y, lo.y);
            split_tf32(wv.z, hi.z, lo.z);
            split_tf32(wv.w, hi.w, lo.w);
            *(uint4*)&Whi_s[row * SS + scol] = hi;
            *(uint4*)&Wlo_s[row * SS + scol] = lo;
        }
        __syncthreads();

        // ---- 4 k-steps of 8: pure LDS + MMA ----
#pragma unroll
        for (int ks = 0; ks < 4; ks++) {
            const int kk = ks * 8 + (lane & 3);

            uint32_t Ahi[2][4], Alo[2][4];
#pragma unroll
            for (int mt = 0; mt < 2; mt++) {
                int r0 = (warp_m * 32 + mt * 16 + (lane >> 2)) * SS;
                Ahi[mt][0] = Ahi_s[r0 + kk];
                Ahi[mt][1] = Ahi_s[r0 + 8 * SS + kk];
                Ahi[mt][2] = Ahi_s[r0 + kk + 4];
                Ahi[mt][3] = Ahi_s[r0 + 8 * SS + kk + 4];
                Alo[mt][0] = Alo_s[r0 + kk];
                Alo[mt][1] = Alo_s[r0 + 8 * SS + kk];
                Alo[mt][2] = Alo_s[r0 + kk + 4];
                Alo[mt][3] = Alo_s[r0 + 8 * SS + kk + 4];
            }

#pragma unroll
            for (int nt = 0; nt < 8; nt++) {
                int n0 = (warp_n * 64 + nt * 8 + (lane >> 2)) * SS;
                uint32_t Bhi0 = Whi_s[n0 + kk];
                uint32_t Bhi1 = Whi_s[n0 + kk + 4];
                uint32_t Blo0 = Wlo_s[n0 + kk];
                uint32_t Blo1 = Wlo_s[n0 + kk + 4];
#pragma unroll
                for (int mt = 0; mt < 2; mt++) {
                    mma8(acc[mt][nt], Ahi[mt][0], Ahi[mt][1], Ahi[mt][2], Ahi[mt][3], Bhi0, Bhi1);
                    mma8(acc[mt][nt], Ahi[mt][0], Ahi[mt][1], Ahi[mt][2], Ahi[mt][3], Blo0, Blo1);
                    mma8(acc[mt][nt], Alo[mt][0], Alo[mt][1], Alo[mt][2], Alo[mt][3], Bhi0, Bhi1);
                }
            }
        }
        __syncthreads();
    }

    // ---- epilogue ----
    float* Cout = (MODE == 0) ? g_h : C;
#pragma unroll
    for (int mt = 0; mt < 2; mt++) {
#pragma unroll
        for (int nt = 0; nt < 8; nt++) {
            int row0 = m0 + warp_m * 32 + mt * 16 + (lane >> 2);
            int col  = warp_n * 64 + nt * 8 + 2 * (lane & 3);
            float2 bv = *(const float2*)&bias[col];
            float o0 = acc[mt][nt][0] + bv.x;
            float o1 = acc[mt][nt][1] + bv.y;
            float o2 = acc[mt][nt][2] + bv.x;
            float o3 = acc[mt][nt][3] + bv.y;
            if (MODE == 0) {
                o0 = fmaxf(o0, 0.f); o1 = fmaxf(o1, 0.f);
                o2 = fmaxf(o2, 0.f); o3 = fmaxf(o3, 0.f);
            }
            if (row0 < NN) {
                float2 w0 = {o0, o1};
                *(float2*)&Cout[row0 * DIM + col] = w0;
            }
            if (row0 + 8 < NN) {
                float2 w1 = {o2, o3};
                *(float2*)&Cout[(row0 + 8) * DIM + col] = w1;
            }
        }
    }
}

// ---------------------------------------------------------------------------
// Scatter: one warp per edge. Lane l reads float4 of h[src], red.add.v4 into
// agg[dst]. Lane 0 bumps deg[dst]. edge_index is int32.
// ---------------------------------------------------------------------------
__global__ __launch_bounds__(256)
void scatter_kernel(const int* __restrict__ ei)
{
    int w    = (blockIdx.x * blockDim.x + threadIdx.x) >> 5;
    int lane = threadIdx.x & 31;
    if (w >= NE) return;

    int s = ei[w];
    int d = ei[NE + w];
    s = min(max(s, 0), NN - 1);
    d = min(max(d, 0), NN - 1);

    const float4* hrow = (const float4*)&g_h[(size_t)s * DIM];
    float4 v = hrow[lane];

    float* dstp = &g_agg[(size_t)d * DIM + lane * 4];
    asm volatile("red.global.add.v4.f32 [%0], {%1, %2, %3, %4};"
                 :: "l"(dstp), "f"(v.x), "f"(v.y), "f"(v.z), "f"(v.w)
                 : "memory");

    if (lane == 0) atomicAdd(&g_deg[d], 1.0f);
}

// ---------------------------------------------------------------------------
extern "C" void kernel_launch(void* const* d_in, const int* in_sizes, int n_in,
                              void* d_out, int out_size)
{
    const float* x  = (const float*)d_in[0];
    const int*   ei = (const int*)d_in[1];
    const float* W1 = (const float*)d_in[2];
    const float* b1 = (const float*)d_in[3];
    const float* W2 = (const float*)d_in[4];
    const float* b2 = (const float*)d_in[5];
    float*       out = (float*)d_out;

    const int SMEM_BYTES = 4 * 128 * SS * 4;   // 73728

    cudaFuncSetAttribute(gemm_tc<0>, cudaFuncAttributeMaxDynamicSharedMemorySize, SMEM_BYTES);
    cudaFuncSetAttribute(gemm_tc<1>, cudaFuncAttributeMaxDynamicSharedMemorySize, SMEM_BYTES);

    void* aggp = nullptr;
    void* degp = nullptr;
    cudaGetSymbolAddress(&aggp, g_agg);
    cudaGetSymbolAddress(&degp, g_deg);
    cudaMemsetAsync(aggp, 0, (size_t)NN * DIM * sizeof(float));
    cudaMemsetAsync(degp, 0, (size_t)NN * sizeof(float));

    int mtiles = (NN + 127) / 128;

    // h = relu(x @ W1^T + b1) -> g_h
    gemm_tc<0><<<mtiles, 256, SMEM_BYTES>>>(x, W1, b1, nullptr);

    // agg += h[src] per edge; deg += 1
    long long total_threads = (long long)NE * 32;
    int blocks = (int)((total_threads + 255) / 256);
    scatter_kernel<<<blocks, 256>>>(ei);

    // out = (agg/deg + h) @ W2^T + b2
    gemm_tc<1><<<mtiles, 256, SMEM_BYTES>>>(nullptr, W2, b2, out);
}